// round 2
// baseline (speedup 1.0000x reference)
#include <cuda_runtime.h>
#include <math.h>

#define Bn 512
#define Kn 512
#define Un 3
#define Hn 128
#define Ln 32
#define NSt 5
#define NPar 5
#define Sn 4
#define NTH 384
#define GRID (Bn/Sn)

struct __align__(16) Smem {
  float4 whh_v[32*384];        // W_hh as [j4][r] float4 over 4 consecutive j
  float h[Sn][Hn];             // hidden state per sample (16B aligned)
  float lift[Sn][Ln];
  float g_r[Sn][Hn];
  float g_z[Sn][Hn];
  float g_xn[Sn][Hn];
  float g_hn[Sn][Hn];
  float w_lift[Ln*6];
  float b_lift_s[Ln];
  float b_ih_s[3*Hn];
  float b_hh_s[3*Hn];
  float w_head[NPar][Hn];
  float b_head_s[NPar];
  float u2y_s[9];
  float feat[Sn][8];
  float dtv[Sn];
  float theta_s[Sn][NPar];
  float ysm[Sn][NSt];
};

__device__ __forceinline__ float sigm(float x){ return 1.0f/(1.0f+expf(-x)); }

__device__ __forceinline__ void rhs5(const float y[5], const float th[5], float d[5]){
  float r1 = th[0]*y[0]*y[1];
  float r2 = th[1]*y[2];
  float r3 = th[2]*y[2]*y[3];
  float r4 = th[3]*y[4];
  float r5 = th[4]*y[0];
  d[0] = -r1 - r5;
  d[1] = -r1 + r2;
  d[2] =  r1 - r2 - r3;
  d[3] = -r3 + r4;
  d[4] =  r3 - r4 + r5;
}

__global__ __launch_bounds__(NTH, 1)
void krnn_kernel(const float* __restrict__ y0, const float* __restrict__ u_seq,
    const float* __restrict__ dt_seq, const float* __restrict__ y_seq,
    const float* __restrict__ W_lift, const float* __restrict__ b_lift,
    const float* __restrict__ W_ih, const float* __restrict__ W_hh,
    const float* __restrict__ b_ih, const float* __restrict__ b_hh,
    const float* __restrict__ W_head, const float* __restrict__ b_head,
    const float* __restrict__ u2y, float* __restrict__ out)
{
  extern __shared__ __align__(16) char smraw[];
  Smem* sm = reinterpret_cast<Smem*>(smraw);
  const int tid = threadIdx.x;
  const int b0 = blockIdx.x * Sn;

  // ---- one-time weight staging ----
  // W_hh (384x128 row-major) -> whh_v[j4*384 + r] = {W[r][4j4..4j4+3]}
  for (int i = tid; i < 384*32; i += NTH) {
    int r = i >> 5, j4 = i & 31;
    sm->whh_v[j4*384 + r] = reinterpret_cast<const float4*>(W_hh)[i];
  }
  // W_ih row r -> registers of thread r
  float wih[Ln];
  {
    const float4* w4 = reinterpret_cast<const float4*>(W_ih) + tid*(Ln/4);
    #pragma unroll
    for (int i = 0; i < Ln/4; i++){
      float4 v = w4[i];
      wih[4*i+0]=v.x; wih[4*i+1]=v.y; wih[4*i+2]=v.z; wih[4*i+3]=v.w;
    }
  }
  for (int i = tid; i < Ln*6;  i += NTH) sm->w_lift[i] = W_lift[i];
  for (int i = tid; i < Ln;    i += NTH) sm->b_lift_s[i] = b_lift[i];
  for (int i = tid; i < 3*Hn;  i += NTH){ sm->b_ih_s[i]=b_ih[i]; sm->b_hh_s[i]=b_hh[i]; }
  for (int i = tid; i < NPar*Hn; i += NTH) (&sm->w_head[0][0])[i] = W_head[i];
  if (tid < NPar) sm->b_head_s[tid] = b_head[tid];
  if (tid < 9)    sm->u2y_s[tid] = u2y[tid];
  for (int i = tid; i < Sn*Hn; i += NTH) (&sm->h[0][0])[i] = 0.0f;
  for (int i = tid; i < Sn*NSt; i += NTH){
    int s = i/NSt, j = i%NSt;
    float v = 0.0f;
    if (j==0) v = y0[(b0+s)*3+0];
    if (j==2) v = y0[(b0+s)*3+1];
    if (j==4) v = y0[(b0+s)*3+2];
    (&sm->ysm[0][0])[i] = v;
  }
  __syncthreads();

  float* out_theta = out + (size_t)Bn*Kn*3;

  for (int k = 0; k < Kn; ++k) {
    // ---- stage 1: feat + dt (threads 0..3, same thread also does RK4 for its sample) ----
    if (tid < Sn) {
      int b = b0 + tid;
      const float* up = u_seq + ((size_t)b*Kn + k)*Un;
      sm->feat[tid][0]=up[0]; sm->feat[tid][1]=up[1]; sm->feat[tid][2]=up[2];
      bool tf = (k > 0) && (k % 50 == 0);
      if (tf) {
        const float* yp = y_seq + ((size_t)b*Kn + (k-1))*3;  // roll(y_seq,1)
        sm->feat[tid][3]=yp[0]; sm->feat[tid][4]=yp[1]; sm->feat[tid][5]=yp[2];
      } else {
        sm->feat[tid][3]=sm->ysm[tid][0];
        sm->feat[tid][4]=sm->ysm[tid][2];
        sm->feat[tid][5]=sm->ysm[tid][4];
      }
      sm->dtv[tid] = dt_seq[(size_t)b*Kn + k];
    }
    __syncthreads();

    // ---- stage 2: lift = silu(feat @ W_lift^T + b) ----
    if (tid < Sn*Ln) {
      int s = tid >> 5, l = tid & 31;
      float a = sm->b_lift_s[l];
      #pragma unroll
      for (int c = 0; c < 6; c++) a = fmaf(sm->w_lift[l*6+c], sm->feat[s][c], a);
      sm->lift[s][l] = a * sigm(a);
    }
    __syncthreads();

    // ---- stage 3: gates. Thread r computes gx[r],gh[r] for all 4 samples ----
    {
      const int r = tid;
      float ax[Sn], ah[Sn];
      float bxv = sm->b_ih_s[r], bhv = sm->b_hh_s[r];
      #pragma unroll
      for (int s=0;s<Sn;s++){ ax[s]=bxv; ah[s]=bhv; }
      #pragma unroll
      for (int l4 = 0; l4 < Ln/4; l4++){
        #pragma unroll
        for (int s=0;s<Sn;s++){
          float4 lv = reinterpret_cast<const float4*>(sm->lift[s])[l4];
          ax[s] = fmaf(wih[4*l4+0], lv.x, ax[s]);
          ax[s] = fmaf(wih[4*l4+1], lv.y, ax[s]);
          ax[s] = fmaf(wih[4*l4+2], lv.z, ax[s]);
          ax[s] = fmaf(wih[4*l4+3], lv.w, ax[s]);
        }
      }
      #pragma unroll 8
      for (int j4 = 0; j4 < Hn/4; j4++){
        float4 w = sm->whh_v[j4*384 + r];
        #pragma unroll
        for (int s=0;s<Sn;s++){
          float4 hv = reinterpret_cast<const float4*>(sm->h[s])[j4];
          ah[s] = fmaf(w.x, hv.x, ah[s]);
          ah[s] = fmaf(w.y, hv.y, ah[s]);
          ah[s] = fmaf(w.z, hv.z, ah[s]);
          ah[s] = fmaf(w.w, hv.w, ah[s]);
        }
      }
      int g = r >> 7, rr = r & 127;
      if (g == 0) {
        #pragma unroll
        for (int s=0;s<Sn;s++) sm->g_r[s][rr] = ax[s] + ah[s];
      } else if (g == 1) {
        #pragma unroll
        for (int s=0;s<Sn;s++) sm->g_z[s][rr] = ax[s] + ah[s];
      } else {  // n-gate: keep gx and gh separate (r multiplies only gh part)
        #pragma unroll
        for (int s=0;s<Sn;s++){ sm->g_xn[s][rr] = ax[s]; sm->g_hn[s][rr] = ah[s]; }
      }
    }
    __syncthreads();

    // ---- stage 4: GRU h update ----
    for (int i = tid; i < Sn*Hn; i += NTH) {
      int s = i >> 7, t = i & 127;
      float rg = sigm(sm->g_r[s][t]);
      float zg = sigm(sm->g_z[s][t]);
      float nn = tanhf(fmaf(rg, sm->g_hn[s][t], sm->g_xn[s][t]));
      sm->h[s][t] = (1.0f - zg)*nn + zg*sm->h[s][t];
    }
    __syncthreads();

    // ---- stage 5: theta head (20 dots of length 128, 8 threads each) ----
    if (tid < Sn*NPar*8) {
      int pair = tid >> 3, j = tid & 7;
      int s = pair / NPar, p = pair % NPar;
      float a = 0.0f;
      #pragma unroll
      for (int m = 0; m < 16; m++)
        a = fmaf(sm->w_head[p][j+8*m], sm->h[s][j+8*m], a);
      a += __shfl_xor_sync(0xffffffffu, a, 4);
      a += __shfl_xor_sync(0xffffffffu, a, 2);
      a += __shfl_xor_sync(0xffffffffu, a, 1);
      if (j == 0) {
        float th = 0.001f + (2.0f - 0.001f)*sigm(a + sm->b_head_s[p]);
        sm->theta_s[s][p] = th;
        out_theta[((size_t)(b0+s)*Kn + k)*NPar + p] = th;
      }
    }
    __syncthreads();

    // ---- stage 6: y_jump + RK4 + outputs (thread s per sample) ----
    if (tid < Sn) {
      int s = tid, b = b0 + s;
      float y[5], th[5];
      #pragma unroll
      for (int j=0;j<5;j++) y[j] = sm->ysm[s][j];
      float u0=sm->feat[s][0], u1=sm->feat[s][1], u2v=sm->feat[s][2];
      y[0] += u0*sm->u2y_s[0] + u1*sm->u2y_s[3] + u2v*sm->u2y_s[6];
      y[2] += u0*sm->u2y_s[1] + u1*sm->u2y_s[4] + u2v*sm->u2y_s[7];
      y[4] += u0*sm->u2y_s[2] + u1*sm->u2y_s[5] + u2v*sm->u2y_s[8];
      #pragma unroll
      for (int p=0;p<5;p++) th[p] = sm->theta_s[s][p];
      float dt = sm->dtv[s];
      float k1[5],k2[5],k3[5],k4[5],yt[5];
      rhs5(y, th, k1);
      #pragma unroll
      for (int j=0;j<5;j++) yt[j] = fmaf(0.5f*dt, k1[j], y[j]);
      rhs5(yt, th, k2);
      #pragma unroll
      for (int j=0;j<5;j++) yt[j] = fmaf(0.5f*dt, k2[j], y[j]);
      rhs5(yt, th, k3);
      #pragma unroll
      for (int j=0;j<5;j++) yt[j] = fmaf(dt, k3[j], y[j]);
      rhs5(yt, th, k4);
      float c = dt*(1.0f/6.0f);
      #pragma unroll
      for (int j=0;j<5;j++){
        float v = y[j] + c*(k1[j] + 2.0f*k2[j] + 2.0f*k3[j] + k4[j]);
        y[j] = fmaxf(v, 0.0f);
        sm->ysm[s][j] = y[j];
      }
      float* oy = out + ((size_t)b*Kn + k)*3;
      oy[0]=y[0]; oy[1]=y[2]; oy[2]=y[4];
    }
    // next iteration's stage-1 writer is the same thread that wrote ysm/feat; the
    // stage-1 trailing __syncthreads orders everything else.
  }
}

extern "C" void kernel_launch(void* const* d_in, const int* in_sizes, int n_in,
                              void* d_out, int out_size) {
  const float* y0     = (const float*)d_in[0];
  const float* u_seq  = (const float*)d_in[1];
  const float* dt_seq = (const float*)d_in[2];
  const float* y_seq  = (const float*)d_in[3];
  const float* W_lift = (const float*)d_in[4];
  const float* b_lift = (const float*)d_in[5];
  const float* W_ih   = (const float*)d_in[6];
  const float* W_hh   = (const float*)d_in[7];
  const float* b_ih   = (const float*)d_in[8];
  const float* b_hh   = (const float*)d_in[9];
  const float* W_head = (const float*)d_in[10];
  const float* b_head = (const float*)d_in[11];
  const float* u2y    = (const float*)d_in[12];
  float* out = (float*)d_out;

  cudaFuncSetAttribute(krnn_kernel, cudaFuncAttributeMaxDynamicSharedMemorySize,
                       (int)sizeof(Smem));
  krnn_kernel<<<GRID, NTH, sizeof(Smem)>>>(y0, u_seq, dt_seq, y_seq, W_lift, b_lift,
                                           W_ih, W_hh, b_ih, b_hh, W_head, b_head,
                                           u2y, out);
}

// round 4
// speedup vs baseline: 1.1268x; 1.1268x over previous
#include <cuda_runtime.h>
#include <math.h>

#define Bn 512
#define Kn 512
#define Un 3
#define Hn 128
#define Ln 32
#define NSt 5
#define NPar 5
#define Sn 4
#define NTH 384
#define GRID (Bn/Sn)

struct __align__(16) Smem {
  float4 whh_v[32*384];        // W_hh as [j4][r] float4 over 4 consecutive j
  float h[Sn][Hn];
  float lift[Sn][Ln];
  float g_r[Sn][Hn];
  float g_z[Sn][Hn];
  float g_xn[Sn][Hn];
  float g_hn[Sn][Hn];
  float w_lift[Ln*6];
  float b_lift_s[Ln];
  float w_head[NPar][Hn];
  float feat[Sn][8];
  float b_head_s[8];
  float u2y_s[12];
  float theta_s[Sn][NPar];
};

__device__ __forceinline__ void ffma2(unsigned long long &acc,
                                      unsigned long long a,
                                      unsigned long long b){
  asm("fma.rn.f32x2 %0, %1, %2, %3;" : "=l"(acc) : "l"(a), "l"(b), "l"(acc));
}
__device__ __forceinline__ float f2sum(unsigned long long v){
  float lo, hi;
  asm("mov.b64 {%0,%1}, %2;" : "=f"(lo), "=f"(hi) : "l"(v));
  return lo + hi;
}

__device__ __forceinline__ float sigm(float x){ return 1.0f/(1.0f+__expf(-x)); }
__device__ __forceinline__ float tanh_f(float x){
  // tanh(x) = 2*sigmoid(2x) - 1 ; abs err ~1e-7, fine vs 1e-3 budget
  return 2.0f/(1.0f+__expf(-2.0f*x)) - 1.0f;
}

__device__ __forceinline__ void rhs5(const float y[5], const float th[5], float d[5]){
  float r1 = th[0]*y[0]*y[1];
  float r2 = th[1]*y[2];
  float r3 = th[2]*y[2]*y[3];
  float r4 = th[3]*y[4];
  float r5 = th[4]*y[0];
  d[0] = -r1 - r5;
  d[1] = -r1 + r2;
  d[2] =  r1 - r2 - r3;
  d[3] = -r3 + r4;
  d[4] =  r3 - r4 + r5;
}

__global__ __launch_bounds__(NTH, 1)
void krnn_kernel(const float* __restrict__ y0, const float* __restrict__ u_seq,
    const float* __restrict__ dt_seq, const float* __restrict__ y_seq,
    const float* __restrict__ W_lift, const float* __restrict__ b_lift,
    const float* __restrict__ W_ih, const float* __restrict__ W_hh,
    const float* __restrict__ b_ih, const float* __restrict__ b_hh,
    const float* __restrict__ W_head, const float* __restrict__ b_head,
    const float* __restrict__ u2y, float* __restrict__ out)
{
  extern __shared__ __align__(16) char smraw[];
  Smem* sm = reinterpret_cast<Smem*>(smraw);
  const int tid = threadIdx.x;
  const int b0 = blockIdx.x * Sn;

  // ---- one-time staging ----
  for (int i = tid; i < 384*32; i += NTH) {
    int r = i >> 5, j4 = i & 31;
    sm->whh_v[j4*384 + r] = reinterpret_cast<const float4*>(W_hh)[i];
  }
  // W_ih row tid -> registers, packed as f32x2 pairs
  ulonglong2 wih2[8];
  {
    const ulonglong2* w4 = reinterpret_cast<const ulonglong2*>(W_ih) + tid*8;
    #pragma unroll
    for (int i = 0; i < 8; i++) wih2[i] = w4[i];
  }
  const float bxv = b_ih[tid];
  const float bhv = b_hh[tid];
  for (int i = tid; i < Ln*6;  i += NTH) sm->w_lift[i] = W_lift[i];
  for (int i = tid; i < Ln;    i += NTH) sm->b_lift_s[i] = b_lift[i];
  for (int i = tid; i < NPar*Hn; i += NTH) (&sm->w_head[0][0])[i] = W_head[i];
  if (tid < NPar) sm->b_head_s[tid] = b_head[tid];
  if (tid < 9)    sm->u2y_s[tid] = u2y[tid];
  for (int i = tid; i < Sn*Hn; i += NTH) (&sm->h[0][0])[i] = 0.0f;

  // y-state + u + dt live in registers of threads 0..3 (sample tid)
  float yst[5] = {0,0,0,0,0};
  float ur0=0.f, ur1=0.f, ur2=0.f, dtr=0.f;
  if (tid < Sn) {
    yst[0] = y0[(b0+tid)*3+0];
    yst[2] = y0[(b0+tid)*3+1];
    yst[4] = y0[(b0+tid)*3+2];
  }
  __syncthreads();

  float* out_theta = out + (size_t)Bn*Kn*3;

  for (int k = 0; k <= Kn; ++k) {
    // ======== TAIL (warps 0-4): finish step k-1, prepare step k ========
    if (tid < 160) {
      if (k > 0) {
        // theta_{k-1} = head(h_new of step k-1)
        int pair = tid >> 3, j = tid & 7;
        int s = pair / NPar, p = pair - NPar*s;
        float a = 0.0f;
        #pragma unroll
        for (int m = 0; m < 16; m++)
          a = fmaf(sm->w_head[p][j+8*m], sm->h[s][j+8*m], a);
        a += __shfl_xor_sync(0xffffffffu, a, 4);
        a += __shfl_xor_sync(0xffffffffu, a, 2);
        a += __shfl_xor_sync(0xffffffffu, a, 1);
        if (j == 0) {
          float th = 0.001f + 1.999f * sigm(a + sm->b_head_s[p]);
          sm->theta_s[s][p] = th;
          out_theta[((size_t)(b0+s)*Kn + (k-1))*NPar + p] = th;
        }
      }
      asm volatile("bar.sync 1, 160;" ::: "memory");
      if (tid < Sn) {
        int s = tid, b = b0 + s;
        if (k > 0) {
          // y_jump with u_{k-1} (registers), then RK4 with theta_{k-1}, dt_{k-1}
          float y[5], th[5];
          #pragma unroll
          for (int j=0;j<5;j++) y[j] = yst[j];
          y[0] += ur0*sm->u2y_s[0] + ur1*sm->u2y_s[3] + ur2*sm->u2y_s[6];
          y[2] += ur0*sm->u2y_s[1] + ur1*sm->u2y_s[4] + ur2*sm->u2y_s[7];
          y[4] += ur0*sm->u2y_s[2] + ur1*sm->u2y_s[5] + ur2*sm->u2y_s[8];
          #pragma unroll
          for (int p=0;p<5;p++) th[p] = sm->theta_s[s][p];
          float k1[5],k2[5],k3[5],k4[5],yt[5];
          rhs5(y, th, k1);
          #pragma unroll
          for (int j=0;j<5;j++) yt[j] = fmaf(0.5f*dtr, k1[j], y[j]);
          rhs5(yt, th, k2);
          #pragma unroll
          for (int j=0;j<5;j++) yt[j] = fmaf(0.5f*dtr, k2[j], y[j]);
          rhs5(yt, th, k3);
          #pragma unroll
          for (int j=0;j<5;j++) yt[j] = fmaf(dtr, k3[j], y[j]);
          rhs5(yt, th, k4);
          float c = dtr*(1.0f/6.0f);
          #pragma unroll
          for (int j=0;j<5;j++){
            float v = y[j] + c*(k1[j] + 2.0f*k2[j] + 2.0f*k3[j] + k4[j]);
            yst[j] = fmaxf(v, 0.0f);
          }
          float* oy = out + ((size_t)b*Kn + (k-1))*3;
          oy[0]=yst[0]; oy[1]=yst[2]; oy[2]=yst[4];
        }
        if (k < Kn) {
          // load u_k, dt_k; build feat_k
          const float* up = u_seq + ((size_t)b*Kn + k)*Un;
          ur0 = up[0]; ur1 = up[1]; ur2 = up[2];
          dtr = dt_seq[(size_t)b*Kn + k];
          sm->feat[s][0]=ur0; sm->feat[s][1]=ur1; sm->feat[s][2]=ur2;
          bool tf = (k > 0) && (k % 50 == 0);
          if (tf) {
            const float* yp = y_seq + ((size_t)b*Kn + (k-1))*3;
            sm->feat[s][3]=yp[0]; sm->feat[s][4]=yp[1]; sm->feat[s][5]=yp[2];
          } else {
            sm->feat[s][3]=yst[0]; sm->feat[s][4]=yst[2]; sm->feat[s][5]=yst[4];
          }
        }
      }
      asm volatile("bar.sync 1, 160;" ::: "memory");
      if (tid < Sn*Ln && k < Kn) {
        int s = tid >> 5, l = tid & 31;
        float a = sm->b_lift_s[l];
        #pragma unroll
        for (int c = 0; c < 6; c++) a = fmaf(sm->w_lift[l*6+c], sm->feat[s][c], a);
        sm->lift[s][l] = a * sigm(a);
      }
    }
    if (k == Kn) break;

    // ======== ah = W_hh_row . h  (all threads, f32x2 packed) ========
    unsigned long long a0[Sn], a1[Sn];
    #pragma unroll
    for (int s=0;s<Sn;s++){ a0[s]=0ull; a1[s]=0ull; }
    {
      const ulonglong2* wp = reinterpret_cast<const ulonglong2*>(sm->whh_v) + tid;
      #pragma unroll 8
      for (int j4 = 0; j4 < Hn/4; j4++){
        ulonglong2 w = wp[j4*384];
        #pragma unroll
        for (int s=0;s<Sn;s++){
          ulonglong2 hv = reinterpret_cast<const ulonglong2*>(sm->h[s])[j4];
          ffma2(a0[s], w.x, hv.x);
          ffma2(a1[s], w.y, hv.y);
        }
      }
    }
    __syncthreads();   // lift_k ready; all h reads done

    // ======== ax = W_ih_row . lift  (f32x2) + gate write ========
    {
      unsigned long long x0[Sn], x1[Sn];
      #pragma unroll
      for (int s=0;s<Sn;s++){ x0[s]=0ull; x1[s]=0ull; }
      #pragma unroll
      for (int l4 = 0; l4 < Ln/4; l4++){
        #pragma unroll
        for (int s=0;s<Sn;s++){
          ulonglong2 lv = reinterpret_cast<const ulonglong2*>(sm->lift[s])[l4];
          ffma2(x0[s], wih2[l4].x, lv.x);
          ffma2(x1[s], wih2[l4].y, lv.y);
        }
      }
      int g = tid >> 7, rr = tid & 127;
      if (g == 0) {
        #pragma unroll
        for (int s=0;s<Sn;s++)
          sm->g_r[s][rr] = (f2sum(x0[s])+f2sum(x1[s])+bxv) + (f2sum(a0[s])+f2sum(a1[s])+bhv);
      } else if (g == 1) {
        #pragma unroll
        for (int s=0;s<Sn;s++)
          sm->g_z[s][rr] = (f2sum(x0[s])+f2sum(x1[s])+bxv) + (f2sum(a0[s])+f2sum(a1[s])+bhv);
      } else {
        #pragma unroll
        for (int s=0;s<Sn;s++){
          sm->g_xn[s][rr] = f2sum(x0[s])+f2sum(x1[s])+bxv;
          sm->g_hn[s][rr] = f2sum(a0[s])+f2sum(a1[s])+bhv;
        }
      }
    }
    __syncthreads();

    // ======== GRU h update ========
    for (int i = tid; i < Sn*Hn; i += NTH) {
      int s = i >> 7, t = i & 127;
      float rg = sigm(sm->g_r[s][t]);
      float zg = sigm(sm->g_z[s][t]);
      float nn = tanh_f(fmaf(rg, sm->g_hn[s][t], sm->g_xn[s][t]));
      sm->h[s][t] = (1.0f - zg)*nn + zg*sm->h[s][t];
    }
    __syncthreads();   // h_new ready for next iter's head + ah
  }
}

extern "C" void kernel_launch(void* const* d_in, const int* in_sizes, int n_in,
                              void* d_out, int out_size) {
  const float* y0     = (const float*)d_in[0];
  const float* u_seq  = (const float*)d_in[1];
  const float* dt_seq = (const float*)d_in[2];
  const float* y_seq  = (const float*)d_in[3];
  const float* W_lift = (const float*)d_in[4];
  const float* b_lift = (const float*)d_in[5];
  const float* W_ih   = (const float*)d_in[6];
  const float* W_hh   = (const float*)d_in[7];
  const float* b_ih   = (const float*)d_in[8];
  const float* b_hh   = (const float*)d_in[9];
  const float* W_head = (const float*)d_in[10];
  const float* b_head = (const float*)d_in[11];
  const float* u2y    = (const float*)d_in[12];
  float* out = (float*)d_out;

  cudaFuncSetAttribute(krnn_kernel, cudaFuncAttributeMaxDynamicSharedMemorySize,
                       (int)sizeof(Smem));
  krnn_kernel<<<GRID, NTH, sizeof(Smem)>>>(y0, u_seq, dt_seq, y_seq, W_lift, b_lift,
                                           W_ih, W_hh, b_ih, b_hh, W_head, b_head,
                                           u2y, out);
}